// round 4
// baseline (speedup 1.0000x reference)
#include <cuda_runtime.h>
#include <cstdint>

// Fixed shapes
#define TT   16
#define HH   1280
#define WW   1280
#define NB   64
#define W4   (WW / 4)            // 320 float4 per row
#define HW4  (HH * W4)           // 409,600 float4 per frame
#define NTHR W4                  // 320 threads: one float4 (4 cols) per thread
#define NBLK HH                  // one block per row
#define NWARP (NTHR / 32)        // 10 warps

// Scratch (device globals — no allocation allowed). xmask 16B-aligned for
// ulonglong2 loads.
__device__ __align__(16) unsigned long long g_ymask[HH];
__device__ __align__(16) unsigned long long g_xmask[WW];
__device__ double       g_acc;
__device__ unsigned int g_count;

// ---------------------------------------------------------------------------
// Kernel 1: per-row / per-column 64-bit box coverage masks.
// Boxes staged in shared; ~6 ALU inst per box per thread. Also zeroes the
// global accumulator state (runs first in the graph on every replay).
// ---------------------------------------------------------------------------
__global__ void masks_kernel(const int* __restrict__ boxes) {
    __shared__ int4 sb[NB];
    const int t = threadIdx.x;
    const int i = blockIdx.x * blockDim.x + t;
    if (t < NB) sb[t] = reinterpret_cast<const int4*>(boxes)[t];
    if (i == 0) { g_acc = 0.0; g_count = 0u; }
    __syncthreads();
    if (i >= HH) return;                       // HH == WW
    unsigned long long ym = 0ull, xm = 0ull;
#pragma unroll
    for (int n = 0; n < NB; n++) {
        int4 b = sb[n];                        // x1, y1, x2, y2
        ym |= (unsigned long long)((unsigned)(i - b.y) < (unsigned)(b.w - b.y)) << n;
        xm |= (unsigned long long)((unsigned)(i - b.x) < (unsigned)(b.z - b.x)) << n;
    }
    g_ymask[i] = ym;
    g_xmask[i] = xm;
}

// ---------------------------------------------------------------------------
// Kernel 2: barrier-free weighted streaming reduction.
// block = one row y; thread = one float4 (4 columns). Weight per column =
// popc(ymask[y] & xmask[x]); 16 frame loads with 8 prefetched for MLP.
// Last finished block writes the scalar output.
// ---------------------------------------------------------------------------
__global__ void __launch_bounds__(NTHR) reduce_kernel(const float* __restrict__ data,
                                                      float* __restrict__ out) {
    const int tid = threadIdx.x;               // 0..319
    const int y   = blockIdx.x;

    // ---- issue the first 8 frame loads immediately (HBM busy from cycle 0) ----
    const float4* p = reinterpret_cast<const float4*>(data) + (size_t)y * W4 + tid;
    float4 v0 = __ldg(p + 0 * (size_t)HW4);
    float4 v1 = __ldg(p + 1 * (size_t)HW4);
    float4 v2 = __ldg(p + 2 * (size_t)HW4);
    float4 v3 = __ldg(p + 3 * (size_t)HW4);
    float4 v4 = __ldg(p + 4 * (size_t)HW4);
    float4 v5 = __ldg(p + 5 * (size_t)HW4);
    float4 v6 = __ldg(p + 6 * (size_t)HW4);
    float4 v7 = __ldg(p + 7 * (size_t)HW4);

    // ---- weights: warp-uniform ymask, vectorized xmask, 4x popc ----
    const unsigned long long ym = __ldg(&g_ymask[y]);
    const ulonglong2 xa = *reinterpret_cast<const ulonglong2*>(&g_xmask[4 * tid]);
    const ulonglong2 xb = *reinterpret_cast<const ulonglong2*>(&g_xmask[4 * tid + 2]);
    const float w0 = (float)__popcll(ym & xa.x);
    const float w1 = (float)__popcll(ym & xa.y);
    const float w2 = (float)__popcll(ym & xb.x);
    const float w3 = (float)__popcll(ym & xb.y);

    // ---- accumulate 16 frames (two banks for ILP) ----
    float a0 = (v0.x + v1.x) + (v2.x + v3.x);
    float a1 = (v0.y + v1.y) + (v2.y + v3.y);
    float a2 = (v0.z + v1.z) + (v2.z + v3.z);
    float a3 = (v0.w + v1.w) + (v2.w + v3.w);
    float b0 = (v4.x + v5.x) + (v6.x + v7.x);
    float b1 = (v4.y + v5.y) + (v6.y + v7.y);
    float b2 = (v4.z + v5.z) + (v6.z + v7.z);
    float b3 = (v4.w + v5.w) + (v6.w + v7.w);
#pragma unroll
    for (int t = 8; t < TT; t += 2) {
        float4 qa = __ldg(p + (size_t)t * HW4);
        float4 qb = __ldg(p + (size_t)(t + 1) * HW4);
        a0 += qa.x; a1 += qa.y; a2 += qa.z; a3 += qa.w;
        b0 += qb.x; b1 += qb.y; b2 += qb.z; b3 += qb.w;
    }

    float s = fmaf(w0, a0 + b0, fmaf(w1, a1 + b1, fmaf(w2, a2 + b2, w3 * (a3 + b3))));

    // ---- warp reduce ----
#pragma unroll
    for (int off = 16; off > 0; off >>= 1)
        s += __shfl_down_sync(0xFFFFFFFFu, s, off);

    // ---- block reduce + global accumulate ----
    __shared__ float warp_sums[NWARP];
    const int lane = tid & 31;
    const int wid  = tid >> 5;
    if (lane == 0) warp_sums[wid] = s;
    __syncthreads();
    if (tid == 0) {
        float b = warp_sums[0];
#pragma unroll
        for (int i = 1; i < NWARP; i++) b += warp_sums[i];

        atomicAdd(&g_acc, (double)b);
        __threadfence();
        unsigned old = atomicAdd(&g_count, 1u);
        if (old == NBLK - 1u) {
            __threadfence();
            out[0] = (float)atomicAdd(&g_acc, 0.0);
        }
    }
}

extern "C" void kernel_launch(void* const* d_in, const int* in_sizes, int n_in,
                              void* d_out, int out_size) {
    const float* data  = (const float*)d_in[0];  // (16,1280,1280) fp32
    const int*   boxes = (const int*)d_in[1];    // (64,4) int32 [x1,y1,x2,y2]
    float*       out   = (float*)d_out;

    masks_kernel<<<(HH + 255) / 256, 256>>>(boxes);
    reduce_kernel<<<NBLK, NTHR>>>(data, out);
}

// round 5
// speedup vs baseline: 1.1230x; 1.1230x over previous
#include <cuda_runtime.h>
#include <cstdint>

// Fixed shapes
#define TT     16
#define TSPLIT 2
#define TPB    (TT / TSPLIT)     // 8 frames per block
#define HH     1280
#define WW     1280
#define NB     64
#define W4     (WW / 4)          // 320 float4 per row
#define HW4    (HH * W4)         // 409,600 float4 per frame
#define NTHR   W4                // 320 threads: one float4 (4 cols) per thread
#define NWARP  (NTHR / 32)       // 10 warps
#define NBLK   (HH * TSPLIT)     // 2560 blocks

__device__ double       g_acc   = 0.0;
__device__ unsigned int g_count = 0u;

// ---------------------------------------------------------------------------
// Single kernel. Block = (row y, t-half). 2560 blocks for concurrency.
//   1) front-batch all 8 frame loads (MLP=8 in flight through the scan phase)
//   2) row weights via shared difference array + block prefix scan (~50 inst)
//   3) weighted dot, warp+block reduce, atomicAdd(double)
//   4) last block writes scalar and resets state for the next graph replay
// ---------------------------------------------------------------------------
__global__ void __launch_bounds__(NTHR, 4) fused_kernel(const float* __restrict__ data,
                                                        const int*   __restrict__ boxes,
                                                        float* __restrict__ out) {
    __shared__ int   sdiff[WW];
    __shared__ int   wsum[NWARP];
    __shared__ float warp_sums[NWARP];

    const int tid  = threadIdx.x;        // 0..319
    const int y    = blockIdx.x;         // row
    const int th   = blockIdx.y;         // t-half (0 or 1)
    const int lane = tid & 31;
    const int wid  = tid >> 5;

    // ---- front-batch this block's 8 frame loads ----
    const float4* p = reinterpret_cast<const float4*>(data)
                      + (size_t)(th * TPB) * HW4 + (size_t)y * W4 + tid;
    float4 v0 = __ldg(p + 0 * (size_t)HW4);
    float4 v1 = __ldg(p + 1 * (size_t)HW4);
    float4 v2 = __ldg(p + 2 * (size_t)HW4);
    float4 v3 = __ldg(p + 3 * (size_t)HW4);
    float4 v4 = __ldg(p + 4 * (size_t)HW4);
    float4 v5 = __ldg(p + 5 * (size_t)HW4);
    float4 v6 = __ldg(p + 6 * (size_t)HW4);
    float4 v7 = __ldg(p + 7 * (size_t)HW4);

    // ---- weights: difference array + block scan (overlapped with loads) ----
    reinterpret_cast<int4*>(sdiff)[tid] = make_int4(0, 0, 0, 0);
    __syncthreads();

    if (tid < NB) {
        int4 b = __ldg(reinterpret_cast<const int4*>(boxes) + tid); // x1,y1,x2,y2
        if (b.y <= y && y < b.w) {
            atomicAdd(&sdiff[b.x],  1);
            atomicAdd(&sdiff[b.z], -1);     // x2 <= 1279 < WW
        }
    }
    __syncthreads();

    int4 c = reinterpret_cast<const int4*>(sdiff)[tid];
    int s0 = c.x, s1 = s0 + c.y, s2 = s1 + c.z, s3 = s2 + c.w;
    const int tot = s3;

    int v = tot;
#pragma unroll
    for (int off = 1; off < 32; off <<= 1) {
        int n = __shfl_up_sync(0xFFFFFFFFu, v, off);
        if (lane >= off) v += n;
    }
    if (lane == 31) wsum[wid] = v;
    __syncthreads();

    int wprefix = 0;
#pragma unroll
    for (int i = 0; i < NWARP; i++)
        if (i < wid) wprefix += wsum[i];
    const int base = wprefix + (v - tot);   // exclusive prefix before this thread

    const float w0 = (float)(base + s0);
    const float w1 = (float)(base + s1);
    const float w2 = (float)(base + s2);
    const float w3 = (float)(base + s3);

    // ---- accumulate the 8 frames (two banks for ILP) ----
    float a0 = (v0.x + v1.x) + (v2.x + v3.x);
    float a1 = (v0.y + v1.y) + (v2.y + v3.y);
    float a2 = (v0.z + v1.z) + (v2.z + v3.z);
    float a3 = (v0.w + v1.w) + (v2.w + v3.w);
    float b0 = (v4.x + v5.x) + (v6.x + v7.x);
    float b1 = (v4.y + v5.y) + (v6.y + v7.y);
    float b2 = (v4.z + v5.z) + (v6.z + v7.z);
    float b3 = (v4.w + v5.w) + (v6.w + v7.w);

    float s = fmaf(w0, a0 + b0, fmaf(w1, a1 + b1, fmaf(w2, a2 + b2, w3 * (a3 + b3))));

    // ---- warp reduce ----
#pragma unroll
    for (int off = 16; off > 0; off >>= 1)
        s += __shfl_down_sync(0xFFFFFFFFu, s, off);
    if (lane == 0) warp_sums[wid] = s;
    __syncthreads();

    if (tid == 0) {
        float b = warp_sums[0];
#pragma unroll
        for (int i = 1; i < NWARP; i++) b += warp_sums[i];

        atomicAdd(&g_acc, (double)b);
        __threadfence();
        unsigned old = atomicAdd(&g_count, 1u);
        if (old == NBLK - 1u) {
            __threadfence();
            double total = atomicAdd(&g_acc, 0.0);
            out[0] = (float)total;
            g_acc = 0.0;                    // reset for next graph replay
            __threadfence();
            g_count = 0u;
        }
    }
}

extern "C" void kernel_launch(void* const* d_in, const int* in_sizes, int n_in,
                              void* d_out, int out_size) {
    const float* data  = (const float*)d_in[0];  // (16,1280,1280) fp32
    const int*   boxes = (const int*)d_in[1];    // (64,4) int32 [x1,y1,x2,y2]
    float*       out   = (float*)d_out;

    dim3 grid(HH, TSPLIT);
    fused_kernel<<<grid, NTHR>>>(data, boxes, out);
}

// round 6
// speedup vs baseline: 1.3283x; 1.1827x over previous
#include <cuda_runtime.h>
#include <cstdint>

// Fixed shapes
#define TT   16
#define HH   1280
#define WW   1280
#define NB   64
#define W4   (WW / 4)            // 320 float4 per row
#define HW4  (HH * W4)           // 409,600 float4 per frame
#define NTHR W4                  // 320 threads: one float4 (4 cols) per thread
#define NBLK HH                  // one block per row
#define NWARP (NTHR / 32)        // 10 warps

__device__ double       g_acc   = 0.0;
__device__ unsigned int g_count = 0u;

// ---------------------------------------------------------------------------
// One block per row y, 5 blocks/SM (launch_bounds caps regs at 40):
//   1) prefetch 4 frames (16 regs live across the scan phase)
//   2) row weights via shared difference array + block prefix scan
//   3) remaining 12 frames in 3 batches of 4, folded into 4 accumulators
//   4) warp+block reduce -> one atomicAdd(double)/block; last block writes out
// ---------------------------------------------------------------------------
__global__ void __launch_bounds__(NTHR, 5) fused_kernel(const float* __restrict__ data,
                                                        const int*   __restrict__ boxes,
                                                        float* __restrict__ out) {
    __shared__ int   sdiff[WW];
    __shared__ int   wsum[NWARP];
    __shared__ float warp_sums[NWARP];

    const int tid  = threadIdx.x;        // 0..319
    const int y    = blockIdx.x;         // row
    const int lane = tid & 31;
    const int wid  = tid >> 5;

    // ---- prefetch 4 frames (in flight through the whole scan phase) ----
    const float4* p = reinterpret_cast<const float4*>(data) + (size_t)y * W4 + tid;
    float4 v0 = __ldg(p + 0 * (size_t)HW4);
    float4 v1 = __ldg(p + 1 * (size_t)HW4);
    float4 v2 = __ldg(p + 2 * (size_t)HW4);
    float4 v3 = __ldg(p + 3 * (size_t)HW4);

    // ---- weights: difference array + block scan ----
    reinterpret_cast<int4*>(sdiff)[tid] = make_int4(0, 0, 0, 0);
    __syncthreads();

    if (tid < NB) {
        int4 b = __ldg(reinterpret_cast<const int4*>(boxes) + tid); // x1,y1,x2,y2
        if (b.y <= y && y < b.w) {
            atomicAdd(&sdiff[b.x],  1);
            atomicAdd(&sdiff[b.z], -1);      // x2 <= 1279 < WW
        }
    }
    __syncthreads();

    int4 c = reinterpret_cast<const int4*>(sdiff)[tid];
    int s0 = c.x, s1 = s0 + c.y, s2 = s1 + c.z, s3 = s2 + c.w;
    const int tot = s3;

    int v = tot;
#pragma unroll
    for (int off = 1; off < 32; off <<= 1) {
        int n = __shfl_up_sync(0xFFFFFFFFu, v, off);
        if (lane >= off) v += n;
    }
    if (lane == 31) wsum[wid] = v;
    __syncthreads();

    int wprefix = 0;
#pragma unroll
    for (int i = 0; i < NWARP; i++)
        if (i < wid) wprefix += wsum[i];
    const int base = wprefix + (v - tot);    // exclusive prefix before this thread

    const float w0 = (float)(base + s0);
    const float w1 = (float)(base + s1);
    const float w2 = (float)(base + s2);
    const float w3 = (float)(base + s3);

    // ---- fold prefetched frames into 4 accumulators ----
    float a0 = (v0.x + v1.x) + (v2.x + v3.x);
    float a1 = (v0.y + v1.y) + (v2.y + v3.y);
    float a2 = (v0.z + v1.z) + (v2.z + v3.z);
    float a3 = (v0.w + v1.w) + (v2.w + v3.w);

    // ---- remaining 12 frames: 3 batches of 4 independent loads ----
#pragma unroll
    for (int t = 4; t < TT; t += 4) {
        float4 q0 = __ldg(p + (size_t)(t + 0) * HW4);
        float4 q1 = __ldg(p + (size_t)(t + 1) * HW4);
        float4 q2 = __ldg(p + (size_t)(t + 2) * HW4);
        float4 q3 = __ldg(p + (size_t)(t + 3) * HW4);
        a0 += (q0.x + q1.x) + (q2.x + q3.x);
        a1 += (q0.y + q1.y) + (q2.y + q3.y);
        a2 += (q0.z + q1.z) + (q2.z + q3.z);
        a3 += (q0.w + q1.w) + (q2.w + q3.w);
    }

    float s = fmaf(w0, a0, fmaf(w1, a1, fmaf(w2, a2, w3 * a3)));

    // ---- warp reduce ----
#pragma unroll
    for (int off = 16; off > 0; off >>= 1)
        s += __shfl_down_sync(0xFFFFFFFFu, s, off);
    if (lane == 0) warp_sums[wid] = s;
    __syncthreads();

    if (tid == 0) {
        float b = warp_sums[0];
#pragma unroll
        for (int i = 1; i < NWARP; i++) b += warp_sums[i];

        atomicAdd(&g_acc, (double)b);
        __threadfence();
        unsigned old = atomicAdd(&g_count, 1u);
        if (old == NBLK - 1u) {
            __threadfence();
            double total = atomicAdd(&g_acc, 0.0);
            out[0] = (float)total;
            g_acc = 0.0;                     // reset for next graph replay
            __threadfence();
            g_count = 0u;
        }
    }
}

extern "C" void kernel_launch(void* const* d_in, const int* in_sizes, int n_in,
                              void* d_out, int out_size) {
    const float* data  = (const float*)d_in[0];  // (16,1280,1280) fp32
    const int*   boxes = (const int*)d_in[1];    // (64,4) int32 [x1,y1,x2,y2]
    float*       out   = (float*)d_out;

    fused_kernel<<<NBLK, NTHR>>>(data, boxes, out);
}